// round 4
// baseline (speedup 1.0000x reference)
#include <cuda_runtime.h>

// NaiveFourierKANLayer: y[b,j] = sum_{i,k} cos(x[b,i]*k)*C0[j,i,k] + sin(x[b,i]*k)*C1[j,i,k] + bias[j]
// N=2048, I=256, J=256, K=300 (k = 1..300)
//
// Strategy: SGEMM with generated A operand (cos/sin features), packed f32x2 FMA
// (sm_100+ FFMA2), 128x128 output tile, 8x8 thread tile, double-buffered smem,
// split-K over the I dimension with atomicAdd accumulation into bias-initialized out.

#define BM 128
#define BN 128
#define KC 8          // k's per smem stage
#define IC 8          // i's per CTA
#define NSPLIT 32     // 256 / IC
#define KTILES 38     // ceil(300/8); last stage has 4 valid k's
#define IDIM 256
#define JDIM 256
#define KGRID 300
#define NTHREADS 256

__device__ __forceinline__ void ffma2(unsigned long long &d,
                                      unsigned long long a,
                                      unsigned long long b) {
    // packed 2x fp32 FMA (sm_100+): d = a*b + d elementwise on (lo,hi)
    asm("fma.rn.f32x2 %0, %1, %2, %0;" : "+l"(d) : "l"(a), "l"(b));
}

__device__ __forceinline__ unsigned long long dup2(float v) {
    unsigned long long r;
    asm("mov.b64 %0, {%1, %1};" : "=l"(r) : "f"(v));
    return r;
}

__global__ void __launch_bounds__(NTHREADS)
fkan_init(float* __restrict__ out, const float* __restrict__ bias, int n) {
    int t = blockIdx.x * blockDim.x + threadIdx.x;
    if (t < n) out[t] = bias[t & (JDIM - 1)];
}

__global__ void __launch_bounds__(NTHREADS, 2)
fkan_gemm(const float* __restrict__ x,
          const float* __restrict__ coeffs,
          float* __restrict__ out)
{
    // smem: [buf][plane][k][row]; planes: F: 0=cos 1=sin ; G: 0=C0 1=C1
    __shared__ __align__(16) float Fsh[2][2][KC][BM];   // 16 KB
    __shared__ __align__(16) float Gsh[2][2][KC][BN];   // 16 KB

    const int t  = threadIdx.x;
    const int tx = t & 15;        // output row group
    const int ty = t >> 4;        // output col group
    const int b0 = blockIdx.x * BM;
    const int j0 = blockIdx.y * BN;
    const int ibase = blockIdx.z * IC;

    // coeff loader mapping: thread owns one (d, j) row, loads 8 k's per stage
    const int ld_d = t >> 7;      // 0 -> C0 (cos), 1 -> C1 (sin)
    const int ld_j = t & 127;
    const float* cbase = coeffs
        + ((size_t)(ld_d * JDIM + j0 + ld_j) * IDIM + ibase) * (size_t)KGRID;

    // feature mapping: thread owns one b-row, computes 4 k's per stage
    const int f_b  = t & 127;
    const int f_kg = (t >> 7) * 4;   // kk base within stage: 0 or 4
    const float* xrow = x + (size_t)(b0 + f_b) * IDIM + ibase;

    unsigned long long acc[8][4];    // [row][jpair] : each u64 = (y_j, y_{j+1})
    #pragma unroll
    for (int i = 0; i < 8; i++)
        #pragma unroll
        for (int j = 0; j < 4; j++) acc[i][j] = 0ULL;

    float4 rA, rB;                   // staged coeff regs for the next stage
    float  xv = xrow[0];
    int    cur_ii = 0;

    // ---- prologue: fill stage 0 directly, preload stage 1 into regs ----
    {
        float4 a = *(const float4*)cbase;          // ii=0, kb=0, k 0..3
        float4 b = *(const float4*)(cbase + 4);    // k 4..7 (kb=0 < 37, valid)
        float va[8] = {a.x, a.y, a.z, a.w, b.x, b.y, b.z, b.w};
        #pragma unroll
        for (int c = 0; c < 8; c++) Gsh[0][ld_d][c][ld_j] = va[c];
        #pragma unroll
        for (int c = 0; c < 4; c++) {
            float kf = (float)(f_kg + c + 1);
            float sn, cs;
            __sincosf(xv * kf, &sn, &cs);          // fp32 x*k matches reference rounding
            Fsh[0][0][f_kg + c][f_b] = cs;
            Fsh[0][1][f_kg + c][f_b] = sn;
        }
        const float* p1 = cbase + KC;              // ii=0, kb=1
        rA = *(const float4*)p1;
        rB = *(const float4*)(p1 + 4);
    }
    __syncthreads();

    int fi = 0, fk = 1;   // (ii,kb) of stage currently held in regs
    int li = 0, lk = 2;   // (ii,kb) of next stage to load

    const int S = IC * KTILES;   // 304 stages

    for (int s = 0; s < S; s++) {
        const int p = s & 1;

        // ---- GEMM on buffer p: 8 k-steps ----
        #pragma unroll
        for (int kk = 0; kk < KC; kk++) {
            // A frags: rows {tx*4+0..3} and {64+tx*4+0..3}  (conflict-free LDS.128)
            float4 c0 = *(const float4*)&Fsh[p][0][kk][tx * 4];
            float4 c1 = *(const float4*)&Fsh[p][0][kk][64 + tx * 4];
            float4 s0 = *(const float4*)&Fsh[p][1][kk][tx * 4];
            float4 s1 = *(const float4*)&Fsh[p][1][kk][64 + tx * 4];
            // B frags: col pairs {ty*4..+3} and {64+ty*4..+3} as packed f32x2
            ulonglong2 g0a = *(const ulonglong2*)&Gsh[p][0][kk][ty * 4];
            ulonglong2 g0b = *(const ulonglong2*)&Gsh[p][0][kk][64 + ty * 4];
            ulonglong2 g1a = *(const ulonglong2*)&Gsh[p][1][kk][ty * 4];
            ulonglong2 g1b = *(const ulonglong2*)&Gsh[p][1][kk][64 + ty * 4];
            unsigned long long cp[4] = {g0a.x, g0a.y, g0b.x, g0b.y};
            unsigned long long sp[4] = {g1a.x, g1a.y, g1b.x, g1b.y};
            float cA[8] = {c0.x, c0.y, c0.z, c0.w, c1.x, c1.y, c1.z, c1.w};
            float sA[8] = {s0.x, s0.y, s0.z, s0.w, s1.x, s1.y, s1.z, s1.w};
            #pragma unroll
            for (int bI = 0; bI < 8; bI++) {
                unsigned long long cd = dup2(cA[bI]);
                unsigned long long sd = dup2(sA[bI]);
                #pragma unroll
                for (int jp = 0; jp < 4; jp++) {
                    ffma2(acc[bI][jp], cd, cp[jp]);   // cos * C0
                    ffma2(acc[bI][jp], sd, sp[jp]);   // sin * C1
                }
            }
        }

        if (s + 1 < S) {
            const int q = p ^ 1;
            // ---- fill stage (fi, fk) into buffer q from staged regs ----
            {
                float va[8] = {rA.x, rA.y, rA.z, rA.w, rB.x, rB.y, rB.z, rB.w};
                #pragma unroll
                for (int c = 0; c < 8; c++) Gsh[q][ld_d][c][ld_j] = va[c];
                if (fi != cur_ii) { xv = xrow[fi]; cur_ii = fi; }
                const float kbase = (float)(fk * KC + f_kg + 1);
                #pragma unroll
                for (int c = 0; c < 4; c++) {
                    float sn, cs;
                    __sincosf(xv * (kbase + (float)c), &sn, &cs);
                    Fsh[q][0][f_kg + c][f_b] = cs;
                    Fsh[q][1][f_kg + c][f_b] = sn;
                }
                fk++; if (fk == KTILES) { fk = 0; fi++; }
            }
            // ---- preload stage (li, lk) into regs (zero-fill k >= 300) ----
            if (s + 2 < S) {
                const float* pp = cbase + (size_t)li * KGRID + lk * KC;
                rA = *(const float4*)pp;
                if (lk < KTILES - 1) rB = *(const float4*)(pp + 4);
                else                 rB = make_float4(0.f, 0.f, 0.f, 0.f);
                lk++; if (lk == KTILES) { lk = 0; li++; }
            }
        }
        __syncthreads();
    }

    // ---- epilogue: split-K accumulate via fp32 REDG ----
    #pragma unroll
    for (int bI = 0; bI < 8; bI++) {
        int row = b0 + ((bI < 4) ? (tx * 4 + bI) : (64 + tx * 4 + bI - 4));
        float* orow = out + (size_t)row * JDIM + j0;
        #pragma unroll
        for (int jp = 0; jp < 4; jp++) {
            int col = (jp < 2) ? (ty * 4 + 2 * jp) : (64 + ty * 4 + 2 * (jp - 2));
            float lo, hi;
            asm("mov.b64 {%0, %1}, %2;" : "=f"(lo), "=f"(hi) : "l"(acc[bI][jp]));
            atomicAdd(orow + col,     lo);
            atomicAdd(orow + col + 1, hi);
        }
    }
}

extern "C" void kernel_launch(void* const* d_in, const int* in_sizes, int n_in,
                              void* d_out, int out_size)
{
    const float* x      = (const float*)d_in[0];   // [2048, 256]
    const float* coeffs = (const float*)d_in[1];   // [2, 256, 256, 300]
    const float* bias   = (const float*)d_in[2];   // [1, 256]
    float* out = (float*)d_out;                    // [2048, 256] fp32

    fkan_init<<<(out_size + NTHREADS - 1) / NTHREADS, NTHREADS>>>(out, bias, out_size);

    dim3 grid(2048 / BM, JDIM / BN, NSPLIT);       // (16, 2, 32) = 1024 CTAs
    fkan_gemm<<<grid, NTHREADS>>>(x, coeffs, out);
}